// round 8
// baseline (speedup 1.0000x reference)
#include <cuda_runtime.h>

// Fast Walsh-Hadamard Transform, N=4096 fp32, one row per 256-thread CTA.
// All 12 stages in registers across 3 rounds; bit ownership chosen so that
// EVERY global memory instruction is lane-contiguous (no strided LDG):
//   round 1: bits {0,1,7,8}   loads: LDG.128, warp reads 512B contiguous
//   round 2: bits {2,3,4,5}   via swizzled smem exchange
//   round 3: bits {6,9,10,11} via swizzled smem exchange; scalar coalesced STG
// Smem uses XOR swizzle on float4 slots:  s' = s ^ ((s>>4)&7)  -> all four
// access patterns (vec write, scalar read, scalar write, scalar read) are
// bank-conflict-free.  Output scaled by 2^-6 (normalized Hadamard).
//
// R8: loads DEFAULT (keep 128MB input resident in the 126MB L2 across graph
//     replays); stores __stcs (write-once output evicts first, freeing L2
//     capacity for the input). launch_bounds(256,6) — oe=8 caused L1tex
//     queue spread regression in R7.

#define HN       4096
#define NTHREADS 256
#define RPT      16

__global__ __launch_bounds__(NTHREADS, 6)
void fwht_kernel(const float* __restrict__ X, float* __restrict__ Y)
{
    __shared__ float4 s4[HN / 4];              // 16 KB, no padding needed
    float* const sf = reinterpret_cast<float*>(s4);

    const size_t row = blockIdx.x;
    const float* __restrict__ x = X + row * HN;
    float*       __restrict__ y = Y + row * HN;

    const int t = threadIdx.x;
    const int w = t >> 5;          // warp 0..7
    const int l = t & 31;          // lane

    float v[RPT];

    // ---- Round 1 load: instr j reads float4 slot  w*128 + j*32 + l ----
    // (warp-contiguous 512B per instruction -> 4 L1 wavefronts each)
    {
        const float4* __restrict__ xv = reinterpret_cast<const float4*>(x);
        #pragma unroll
        for (int j = 0; j < 4; j++) {
            float4 a = xv[w * 128 + j * 32 + l];
            v[4*j+0] = a.x; v[4*j+1] = a.y; v[4*j+2] = a.z; v[4*j+3] = a.w;
        }
    }
    // reg index r = j*4 + k  maps to n-bits: r0,r1 = n0,n1 ; r2,r3 = n7,n8
    #pragma unroll
    for (int st = 1; st < RPT; st <<= 1) {
        #pragma unroll
        for (int i = 0; i < RPT; i++) {
            if (!(i & st)) {
                float a = v[i], b = v[i ^ st];
                v[i]      = a + b;
                v[i ^ st] = a - b;
            }
        }
    }

    // ---- Exchange 1 write: float4 slot s = w*128 + j*32 + l, swizzled ----
    #pragma unroll
    for (int j = 0; j < 4; j++) {
        int s  = w * 128 + j * 32 + l;
        int ss = s ^ ((s >> 4) & 7);
        s4[ss] = make_float4(v[4*j+0], v[4*j+1], v[4*j+2], v[4*j+3]);
    }
    __syncthreads();

    // ---- Round 2: thread fixes p=n0n1, q=n6, u=n7n8, w=n9..11; i = n2..5 ----
    const int p  = l & 3;
    const int q  = (l >> 2) & 1;
    const int u  = (l >> 3) & 3;
    const int sbase = 16 * q + 32 * u + 128 * w;   // slot base (i adds 0..15)
    const int sig   = q + 2 * u;                   // = ((s>>4)&7) for these slots
    #pragma unroll
    for (int i = 0; i < RPT; i++) {
        int ss = (sbase + i) ^ sig;
        v[i] = sf[ss * 4 + p];
    }
    // reg index i = n-bits 2..5
    #pragma unroll
    for (int st = 1; st < RPT; st <<= 1) {
        #pragma unroll
        for (int i = 0; i < RPT; i++) {
            if (!(i & st)) {
                float a = v[i], b = v[i ^ st];
                v[i]      = a + b;
                v[i ^ st] = a - b;
            }
        }
    }
    // write back to the same (thread-private) addresses — no barrier needed first
    #pragma unroll
    for (int i = 0; i < RPT; i++) {
        int ss = (sbase + i) ^ sig;
        sf[ss * 4 + p] = v[i];
    }
    __syncthreads();

    // ---- Round 3: thread fixes m = n0..5, u2 = n7n8 ; i2 -> {n6, n9..11} ----
    const int u2 = w >> 1;                 // n7,n8
    const int m  = ((w & 1) << 5) | l;     // n0..5
    const int mq = m >> 2;                 // slot low bits
    const int mp = m & 3;
    #pragma unroll
    for (int i2 = 0; i2 < RPT; i2++) {
        int b6 = i2 & 1, hi = i2 >> 1;
        int s  = mq + 16 * b6 + 32 * u2 + 128 * hi;
        int sg = b6 + 2 * u2;              // = ((s>>4)&7)
        v[i2] = sf[(s ^ sg) * 4 + mp];
    }
    // reg index i2: bit0 = n6, bits1..3 = n9..11
    #pragma unroll
    for (int st = 1; st < RPT; st <<= 1) {
        #pragma unroll
        for (int i = 0; i < RPT; i++) {
            if (!(i & st)) {
                float a = v[i], b = v[i ^ st];
                v[i]      = a + b;
                v[i ^ st] = a - b;
            }
        }
    }

    // ---- Store: n = m + 64*b6 + 128*u2 + 512*hi ; lanes contiguous 128B ----
    const int obase = m + 128 * u2;
    #pragma unroll
    for (int i2 = 0; i2 < RPT; i2++) {
        int b6 = i2 & 1, hi = i2 >> 1;
        __stcs(&y[obase + 64 * b6 + 512 * hi], v[i2] * 0.015625f);   // * 2^-6
    }
}

extern "C" void kernel_launch(void* const* d_in, const int* in_sizes, int n_in,
                              void* d_out, int out_size)
{
    const float* X = (const float*)d_in[0];   // [8192, 4096] fp32
    // d_in[1]: dense Hadamard matrix H — unused (FWHT).
    float* Y = (float*)d_out;

    const int rows = in_sizes[0] / HN;        // 8192
    fwht_kernel<<<rows, NTHREADS>>>(X, Y);
}

// round 9
// speedup vs baseline: 1.0007x; 1.0007x over previous
#include <cuda_runtime.h>

// Fast Walsh-Hadamard Transform, N=4096 fp32, one row per 256-thread CTA.
// All 12 stages in registers across 3 rounds; every global memory instruction
// is lane-contiguous:
//   round 1: bits {0,1,7,8}   LDG.128 (warp reads 512B contiguous per instr)
//   round 2: bits {2,3,4,5}   via swizzled smem exchange
//   round 3: bits {6,9,10,11} via swizzled smem exchange; coalesced STG
// XOR swizzle on float4 slots: s' = s ^ ((s>>4)&7) -> all patterns conflict-free.
// Output scaled by 2^-6 (normalized Hadamard).
//
// R9: occupancy 8 (32 regs) + SPLIT round-1 loads: 2 LDG.128, butterfly bits
//     0-1 on that half, then the other 2 LDG.128 (MLP_p1 = 2). Avoids the
//     cross-CTA L1tex-queue spread that killed the occ-8 attempt with a
//     front-batched 4-LDG burst. Loads default (L2-resident X), stores __stcs.

#define HN       4096
#define NTHREADS 256
#define RPT      16

__global__ __launch_bounds__(NTHREADS, 8)
void fwht_kernel(const float* __restrict__ X, float* __restrict__ Y)
{
    __shared__ float4 s4[HN / 4];              // 16 KB
    float* const sf = reinterpret_cast<float*>(s4);

    const size_t row = blockIdx.x;
    const float* __restrict__ x = X + row * HN;
    float*       __restrict__ y = Y + row * HN;

    const int t = threadIdx.x;
    const int w = t >> 5;          // warp 0..7
    const int l = t & 31;          // lane

    float v[RPT];

    // ---- Round 1: reg r = j*4+k maps to n-bits r0,r1 = n0,n1 ; r2,r3 = n7,n8
    // Split loads: 2 LDG.128, compute bits 0-1 on that half, then 2 more.
    {
        const float4* __restrict__ xv = reinterpret_cast<const float4*>(x);
        #pragma unroll
        for (int j = 0; j < 2; j++) {
            float4 a = xv[w * 128 + j * 32 + l];
            v[4*j+0] = a.x; v[4*j+1] = a.y; v[4*j+2] = a.z; v[4*j+3] = a.w;
        }
        // stages st=1,2 (bits n0,n1) on first half (regs 0..7)
        #pragma unroll
        for (int st = 1; st <= 2; st <<= 1) {
            #pragma unroll
            for (int i = 0; i < 8; i++) {
                if (!(i & st)) {
                    float a = v[i], b = v[i ^ st];
                    v[i] = a + b;  v[i ^ st] = a - b;
                }
            }
        }
        #pragma unroll
        for (int j = 2; j < 4; j++) {
            float4 a = xv[w * 128 + j * 32 + l];
            v[4*j+0] = a.x; v[4*j+1] = a.y; v[4*j+2] = a.z; v[4*j+3] = a.w;
        }
        // stages st=1,2 on second half (regs 8..15)
        #pragma unroll
        for (int st = 1; st <= 2; st <<= 1) {
            #pragma unroll
            for (int i = 8; i < 16; i++) {
                if (!(i & st)) {
                    float a = v[i], b = v[i ^ st];
                    v[i] = a + b;  v[i ^ st] = a - b;
                }
            }
        }
        // stages st=4 (n7), st=8 (n8) across all regs
        #pragma unroll
        for (int st = 4; st < RPT; st <<= 1) {
            #pragma unroll
            for (int i = 0; i < RPT; i++) {
                if (!(i & st)) {
                    float a = v[i], b = v[i ^ st];
                    v[i] = a + b;  v[i ^ st] = a - b;
                }
            }
        }
    }

    // ---- Exchange 1 write: float4 slot s = w*128 + j*32 + l, swizzled ----
    #pragma unroll
    for (int j = 0; j < 4; j++) {
        int s  = w * 128 + j * 32 + l;
        int ss = s ^ ((s >> 4) & 7);
        s4[ss] = make_float4(v[4*j+0], v[4*j+1], v[4*j+2], v[4*j+3]);
    }
    __syncthreads();

    // ---- Round 2: thread fixes p=n0n1, q=n6, u=n7n8, w=n9..11; i = n2..5 ----
    const int p  = l & 3;
    const int q  = (l >> 2) & 1;
    const int u  = (l >> 3) & 3;
    const int sbase = 16 * q + 32 * u + 128 * w;
    const int sig   = q + 2 * u;                   // = ((s>>4)&7) for these slots
    #pragma unroll
    for (int i = 0; i < RPT; i++) {
        int ss = (sbase + i) ^ sig;
        v[i] = sf[ss * 4 + p];
    }
    #pragma unroll
    for (int st = 1; st < RPT; st <<= 1) {
        #pragma unroll
        for (int i = 0; i < RPT; i++) {
            if (!(i & st)) {
                float a = v[i], b = v[i ^ st];
                v[i] = a + b;  v[i ^ st] = a - b;
            }
        }
    }
    // write back to the same thread-private addresses (no barrier needed first)
    #pragma unroll
    for (int i = 0; i < RPT; i++) {
        int ss = (sbase + i) ^ sig;
        sf[ss * 4 + p] = v[i];
    }
    __syncthreads();

    // ---- Round 3: thread fixes m = n0..5, u2 = n7n8 ; i2 -> {n6, n9..11} ----
    const int u2 = w >> 1;
    const int m  = ((w & 1) << 5) | l;
    const int mq = m >> 2;
    const int mp = m & 3;
    #pragma unroll
    for (int i2 = 0; i2 < RPT; i2++) {
        int b6 = i2 & 1, hi = i2 >> 1;
        int s  = mq + 16 * b6 + 32 * u2 + 128 * hi;
        int sg = b6 + 2 * u2;
        v[i2] = sf[(s ^ sg) * 4 + mp];
    }
    #pragma unroll
    for (int st = 1; st < RPT; st <<= 1) {
        #pragma unroll
        for (int i = 0; i < RPT; i++) {
            if (!(i & st)) {
                float a = v[i], b = v[i ^ st];
                v[i] = a + b;  v[i ^ st] = a - b;
            }
        }
    }

    // ---- Store: n = m + 64*b6 + 128*u2 + 512*hi ; lanes contiguous 128B ----
    const int obase = m + 128 * u2;
    #pragma unroll
    for (int i2 = 0; i2 < RPT; i2++) {
        int b6 = i2 & 1, hi = i2 >> 1;
        __stcs(&y[obase + 64 * b6 + 512 * hi], v[i2] * 0.015625f);   // * 2^-6
    }
}

extern "C" void kernel_launch(void* const* d_in, const int* in_sizes, int n_in,
                              void* d_out, int out_size)
{
    const float* X = (const float*)d_in[0];   // [8192, 4096] fp32
    // d_in[1]: dense Hadamard matrix H — unused (FWHT).
    float* Y = (float*)d_out;

    const int rows = in_sizes[0] / HN;        // 8192
    fwht_kernel<<<rows, NTHREADS>>>(X, Y);
}